// round 15
// baseline (speedup 1.0000x reference)
#include <cuda_runtime.h>
#include <cuda_bf16.h>
#include <cuda_fp16.h>
#include <math.h>
#include <stdint.h>

#define BB 8
#define QQL 1024
#define KKL 1024
#define DDIM 1024
#define NH 16
#define HDIM 64
#define FFD 4096
#define MROWS (BB*QQL)   /* 8192 */
#define GS 40            /* smem row stride (2B elems) */
#define APLANE (256*GS)
#define BPLANE (128*GS)

// ---------------- scratch (device globals) ----------------
__device__ __half g_xn16[(size_t)2 * MROWS * DDIM];
__device__ __half g_qk16[(size_t)2 * MROWS * DDIM];
__device__ __half g_lnf16[(size_t)MROWS * DDIM];
__device__ __half g_vt16[(size_t)MROWS * DDIM];
__device__ __half g_ao16[(size_t)MROWS * DDIM];
__device__ __half g_h16[(size_t)MROWS * FFD];
__device__ __half g_w16[(size_t)12 * 1024 * 1024];
__device__ __half g_attn16[(size_t)BB * NH * QQL * KKL];     // 256 MB
__device__ float g_v[(size_t)MROWS * DDIM];
__device__ float g_scores[(size_t)BB * NH * QQL * KKL];      // 512 MB
__device__ float g_x[(size_t)MROWS * DDIM];
__device__ int   g_mask_flag;

// ---------------- helpers ----------------
__device__ __forceinline__ uint32_t smem_u32(const void* p) {
    return (uint32_t)__cvta_generic_to_shared(p);
}
__device__ __forceinline__ void cpa16(uint32_t dst, const void* src) {
    asm volatile("cp.async.cg.shared.global [%0], [%1], 16;\n" :: "r"(dst), "l"(src));
}
__device__ __forceinline__ void cpa_commit() { asm volatile("cp.async.commit_group;\n"); }
__device__ __forceinline__ void cpa_wait0() { asm volatile("cp.async.wait_group 0;\n"); }
__device__ __forceinline__ void cpa_wait1() { asm volatile("cp.async.wait_group 1;\n"); }

__device__ __forceinline__ void mma_fp16(float* c, const uint32_t* a, uint32_t b0, uint32_t b1) {
    asm volatile(
        "mma.sync.aligned.m16n8k16.row.col.f32.f16.f16.f32 "
        "{%0,%1,%2,%3}, {%4,%5,%6,%7}, {%8,%9}, {%0,%1,%2,%3};\n"
        : "+f"(c[0]), "+f"(c[1]), "+f"(c[2]), "+f"(c[3])
        : "r"(a[0]), "r"(a[1]), "r"(a[2]), "r"(a[3]), "r"(b0), "r"(b1));
}
__device__ __forceinline__ void ldsm_x4(uint32_t* r, uint32_t addr) {
    asm volatile("ldmatrix.sync.aligned.m8n8.x4.shared.b16 {%0,%1,%2,%3}, [%4];\n"
                 : "=r"(r[0]), "=r"(r[1]), "=r"(r[2]), "=r"(r[3]) : "r"(addr));
}
__device__ __forceinline__ float gelu_exact(float v) {
    return 0.5f * v * (1.0f + erff(v * 0.70710678118654752f));
}

// ---------------- mask dtype sniffing ----------------
__global__ void detect_mask_kernel(const unsigned char* __restrict__ m) {
    __shared__ int c1, c2, c3;
    if (threadIdx.x == 0) { c1 = 0; c2 = 0; c3 = 0; }
    __syncthreads();
    for (int i = threadIdx.x; i < BB * KKL; i += blockDim.x) {
        unsigned char v = m[i];
        if (v) {
            int p = i & 3;
            if (p == 1) atomicAdd(&c1, 1);
            else if (p == 2) atomicAdd(&c2, 1);
            else if (p == 3) atomicAdd(&c3, 1);
        }
    }
    __syncthreads();
    if (threadIdx.x == 0) {
        int f;
        if (c1 == 0 && c2 == 0 && c3 == 0) f = 0;  // int32
        else if (c1 == 0) f = 2;                   // float32
        else f = 1;                                // uint8
        g_mask_flag = f;
    }
}

__device__ __forceinline__ bool mask_valid(const void* m, int idx, int flag) {
    if (flag == 1) return ((const unsigned char*)m)[idx] != 0;
    if (flag == 2) return ((const float*)m)[idx] != 0.0f;
    return ((const int*)m)[idx] != 0;
}

// ---------------- convert fp32 -> fp16 ----------------
__global__ void __launch_bounds__(256) tofp16_kernel(
    const float* __restrict__ x, __half* __restrict__ out, size_t n)
{
    size_t i = ((size_t)blockIdx.x * 256 + threadIdx.x) * 4;
    if (i >= n) return;
    float4 v = *(const float4*)(x + i);
    __half2* op = (__half2*)(out + i);
    op[0] = __floats2half2_rn(v.x, v.y);
    op[1] = __floats2half2_rn(v.z, v.w);
}

// ---------------- layernorm -> fp16 ----------------
__global__ void __launch_bounds__(256) ln_fp16_kernel(
    const float* __restrict__ x, const float* __restrict__ w,
    const float* __restrict__ b, __half* __restrict__ out)
{
    int row = blockIdx.x;
    const float* xr = x + (size_t)row * DDIM;
    float sum = 0.f, sumsq = 0.f;
    for (int i = threadIdx.x; i < DDIM; i += blockDim.x) {
        float v = xr[i]; sum += v; sumsq += v * v;
    }
    __shared__ float s1[32], s2[32];
    for (int o = 16; o; o >>= 1) {
        sum   += __shfl_down_sync(0xffffffffu, sum, o);
        sumsq += __shfl_down_sync(0xffffffffu, sumsq, o);
    }
    int lane = threadIdx.x & 31, wid = threadIdx.x >> 5;
    if (lane == 0) { s1[wid] = sum; s2[wid] = sumsq; }
    __syncthreads();
    if (wid == 0) {
        sum   = lane < 8 ? s1[lane] : 0.f;
        sumsq = lane < 8 ? s2[lane] : 0.f;
        for (int o = 4; o; o >>= 1) {
            sum   += __shfl_down_sync(0xffffffffu, sum, o);
            sumsq += __shfl_down_sync(0xffffffffu, sumsq, o);
        }
        if (lane == 0) { s1[0] = sum; s2[0] = sumsq; }
    }
    __syncthreads();
    float mu  = s1[0] * (1.0f / DDIM);
    float var = s2[0] * (1.0f / DDIM) - mu * mu;
    float inv = rsqrtf(var + 1e-5f);
    size_t base = (size_t)row * DDIM;
    for (int i = threadIdx.x; i < DDIM; i += blockDim.x) {
        float v = (xr[i] - mu) * inv * w[i] + b[i];
        out[base + i] = __float2half_rn(v);
    }
}

// ---------------- fp16 1-pass GEMM, CTA tile 256x128, 512 threads, z-batch ----------------
__global__ void __launch_bounds__(512, 1) gemm16_kernel(
    const __half* __restrict__ A, long lda, long sAz,
    const __half* __restrict__ W, long ldb, long sBz,
    const float* __restrict__ bias, long sbias, const float* __restrict__ resid,
    float* __restrict__ Cf, __half* __restrict__ Chf, long ldc, long sCz,
    int Kd, int act)
{
    extern __shared__ __half smh[];
    const int SP = APLANE + BPLANE;
    const int offB = APLANE;

    const int tid  = threadIdx.x;
    const int lane = tid & 31;
    const int warp = tid >> 5;
    const int wm = warp >> 2, wn = warp & 3;
    const int z = blockIdx.z;
    const size_t Aoff = (size_t)z * sAz;
    const size_t Boff = (size_t)z * sBz;
    const size_t Coff = (size_t)z * sCz;
    const size_t bm = (size_t)blockIdx.y * 256, bn = (size_t)blockIdx.x * 128;
    const float* bptr = bias ? bias + (size_t)z * sbias : nullptr;

    const int lr   = tid >> 2;
    const int lseg = (tid & 3) * 8;
    const __half* gA1 = A + Aoff + (bm + lr) * (size_t)lda + lseg;
    const __half* gA2 = gA1 + 128 * (size_t)lda;
    const __half* gB  = W + Boff + (bn + lr) * (size_t)ldb + lseg;
    const int soffA1 = lr * GS + lseg;
    const int soffA2 = soffA1 + 128 * GS;
    const int soffB  = lr * GS + lseg;

    const uint32_t smBase = smem_u32(smh);
    const int arow = wm * 64 + (lane & 15);
    const int acol = (lane >> 4) << 3;
    const int bg = lane >> 2;
    const int bt = (lane & 3) << 1;

    float acc[4][4][4];
#pragma unroll
    for (int i = 0; i < 4; i++)
#pragma unroll
        for (int j = 0; j < 4; j++)
#pragma unroll
            for (int t = 0; t < 4; t++) acc[i][j][t] = 0.f;

    const int ntiles = Kd >> 5;

    auto load_stage = [&](int st, int k0) {
        uint32_t base = smBase + (uint32_t)(st * SP) * 2;
        cpa16(base + (uint32_t)soffA1 * 2, gA1 + k0);
        cpa16(base + (uint32_t)soffA2 * 2, gA2 + k0);
        cpa16(base + (uint32_t)(offB + soffB) * 2, gB + k0);
    };

    load_stage(0, 0);
    cpa_commit();

    for (int it = 0; it < ntiles; it++) {
        if (it + 1 < ntiles) { load_stage((it + 1) & 1, (it + 1) << 5); cpa_commit(); cpa_wait1(); }
        else cpa_wait0();
        __syncthreads();

        const int st = it & 1;
        const uint32_t aB = smBase + (uint32_t)(st * SP) * 2;
        const __half* sB = smh + st * SP + offB;

#pragma unroll
        for (int ks = 0; ks < 32; ks += 16) {
            uint32_t af[4][4];
#pragma unroll
            for (int mi = 0; mi < 4; mi++) {
                uint32_t off = (uint32_t)(((arow + mi * 16) * GS + ks + acol) * 2);
                ldsm_x4(af[mi], aB + off);
            }
#pragma unroll
            for (int ni = 0; ni < 4; ni++) {
                int bidx = (wn * 32 + ni * 8 + bg) * GS + ks + bt;
                uint32_t b0 = *(const uint32_t*)&sB[bidx];
                uint32_t b1 = *(const uint32_t*)&sB[bidx + 8];
#pragma unroll
                for (int mi = 0; mi < 4; mi++)
                    mma_fp16(acc[mi][ni], af[mi], b0, b1);
            }
        }
        __syncthreads();
    }

    const int gr = lane >> 2;
    const int gc = (lane & 3) << 1;
#pragma unroll
    for (int mi = 0; mi < 4; mi++) {
        size_t r0 = bm + wm * 64 + mi * 16 + gr;
#pragma unroll
        for (int ni = 0; ni < 4; ni++) {
            size_t c0 = bn + wn * 32 + ni * 8 + gc;
            float bv0 = bptr ? bptr[c0] : 0.f;
            float bv1 = bptr ? bptr[c0 + 1] : 0.f;
#pragma unroll
            for (int half = 0; half < 2; half++) {
                size_t row = r0 + half * 8;
                float v0 = acc[mi][ni][half * 2 + 0] + bv0;
                float v1 = acc[mi][ni][half * 2 + 1] + bv1;
                size_t o = Coff + row * ldc + c0;
                if (resid) {
                    float2 rv = *(const float2*)(resid + o);
                    v0 += rv.x; v1 += rv.y;
                }
                if (act) { v0 = gelu_exact(v0); v1 = gelu_exact(v1); }
                if (Cf)  *(float2*)(Cf + o) = make_float2(v0, v1);
                if (Chf) *(__half2*)(Chf + o) = __floats2half2_rn(v0, v1);
            }
        }
    }
}

// ---------------- dedicated fp16 scores kernel (persistent A) ----------------
#define SGS 72
#define SAPL (256*SGS)
#define SBPL (128*SGS)
__global__ void __launch_bounds__(512, 1) scores16_kernel(
    const __half* __restrict__ qp, const __half* __restrict__ kp,
    float* __restrict__ S)
{
    extern __shared__ __half smh[];
    const int offB = SAPL;
    const int BSTG = SBPL;

    const int tid = threadIdx.x, lane = tid & 31, warp = tid >> 5;
    const int wm = warp >> 2, wn = warp & 3;
    const int z = blockIdx.z, b = z / NH, h = z % NH;
    const size_t bm = (size_t)blockIdx.y * 256;
    const __half* A = qp + (size_t)b * QQL * DDIM + h * HDIM;
    const __half* B = kp + (size_t)b * KKL * DDIM + h * HDIM;
    float* C = S + ((size_t)(b * NH + h) * QQL + bm) * KKL;

    const uint32_t smBase = smem_u32(smh);

    // A: 256 rows x 64 cols fp16, persistent
#pragma unroll
    for (int i = 0; i < 4; i++) {
        int c = tid + 512 * i;
        int row = c >> 3;
        int seg = (c & 7) * 8;
        uint32_t d = smBase + (uint32_t)(row * SGS + seg) * 2;
        cpa16(d, A + (bm + row) * (size_t)DDIM + seg);
    }
    auto load_B = [&](int st, int kt) {
        uint32_t base = smBase + (uint32_t)(offB + st * BSTG) * 2;
#pragma unroll
        for (int i = 0; i < 2; i++) {
            int c = tid + 512 * i;
            int row = c >> 3;
            int seg = (c & 7) * 8;
            cpa16(base + (uint32_t)(row * SGS + seg) * 2,
                  B + (size_t)(kt * 128 + row) * DDIM + seg);
        }
    };
    load_B(0, 0);
    cpa_commit();

    const int arow = wm * 64 + (lane & 15);
    const int acol = (lane >> 4) << 3;
    const int bg = lane >> 2, bt = (lane & 3) << 1;
    const int gr = lane >> 2;
    const int gc = (lane & 3) << 1;

    for (int kt = 0; kt < 8; kt++) {
        if (kt + 1 < 8) { load_B((kt + 1) & 1, kt + 1); cpa_commit(); cpa_wait1(); }
        else cpa_wait0();
        __syncthreads();
        const __half* sB = smh + offB + (kt & 1) * BSTG;

        float acc[4][4][4];
#pragma unroll
        for (int i = 0; i < 4; i++)
#pragma unroll
            for (int j = 0; j < 4; j++)
#pragma unroll
                for (int t = 0; t < 4; t++) acc[i][j][t] = 0.f;

#pragma unroll
        for (int ks = 0; ks < 64; ks += 16) {
            uint32_t af[4][4];
#pragma unroll
            for (int mi = 0; mi < 4; mi++) {
                uint32_t off = (uint32_t)(((arow + mi * 16) * SGS + ks + acol) * 2);
                ldsm_x4(af[mi], smBase + off);
            }
#pragma unroll
            for (int ni = 0; ni < 4; ni++) {
                int bidx = (wn * 32 + ni * 8 + bg) * SGS + ks + bt;
                uint32_t b0 = *(const uint32_t*)&sB[bidx];
                uint32_t b1 = *(const uint32_t*)&sB[bidx + 8];
#pragma unroll
                for (int mi = 0; mi < 4; mi++)
                    mma_fp16(acc[mi][ni], af[mi], b0, b1);
            }
        }

#pragma unroll
        for (int mi = 0; mi < 4; mi++) {
            size_t r0 = wm * 64 + mi * 16 + gr;
#pragma unroll
            for (int ni = 0; ni < 4; ni++) {
                size_t c0 = (size_t)kt * 128 + wn * 32 + ni * 8 + gc;
#pragma unroll
                for (int half = 0; half < 2; half++) {
                    size_t row = r0 + half * 8;
                    *(float2*)(C + row * KKL + c0) = make_float2(
                        acc[mi][ni][half * 2 + 0] * 0.125f,
                        acc[mi][ni][half * 2 + 1] * 0.125f);
                }
            }
        }
        __syncthreads();
    }
}

// ---------------- transpose V (fp32 -> fp16, [b,k,c] -> [b,c,k]) ----------------
__global__ void __launch_bounds__(256) transpose16_kernel(
    const float* __restrict__ v, __half* __restrict__ th)
{
    __shared__ float tile[32][33];
    int tx = threadIdx.x, ty = threadIdx.y;
    int c0 = blockIdx.x * 32;
    int r0 = blockIdx.y * 32;
#pragma unroll
    for (int i = 0; i < 4; i++)
        tile[ty + i * 8][tx] = v[(size_t)(r0 + ty + i * 8) * DDIM + c0 + tx];
    __syncthreads();
    int b = r0 >> 10;
    int kk0 = r0 & 1023;
#pragma unroll
    for (int i = 0; i < 4; i++) {
        float val = tile[tx][ty + i * 8];
        size_t o = ((size_t)(b << 10) + c0 + ty + i * 8) * 1024 + kk0 + tx;
        th[o] = __float2half_rn(val);
    }
}

// ---------------- fused masked softmax + head mean (2 heads / iter, fp16 out) ----------------
__global__ void __launch_bounds__(256) softmax_mean_kernel(
    const float* __restrict__ S, const void* __restrict__ mask,
    __half* __restrict__ ah, float* __restrict__ mout)
{
    const int bq = blockIdx.x;
    const int b = bq >> 10, q = bq & 1023;
    const int t = threadIdx.x;
    const int k0 = t * 4;
    const int flag = g_mask_flag;
    const int lane = t & 31, w = t >> 5;

    bool mk[4];
#pragma unroll
    for (int i = 0; i < 4; i++) mk[i] = mask_valid(mask, b * KKL + k0 + i, flag);

    float macc[4] = {0.f, 0.f, 0.f, 0.f};
    __shared__ float red[16];
    const float NEG = -__int_as_float(0x7f800000);

    for (int h = 0; h < NH; h += 2) {
        const float* ra = S + (((size_t)(b * NH + h)) * QQL + q) * KKL;
        const float* rb = ra + (size_t)QQL * KKL;
        float4 a4 = *(const float4*)(ra + k0);
        float4 b4 = *(const float4*)(rb + k0);
        float va[4] = {a4.x, a4.y, a4.z, a4.w};
        float vb[4] = {b4.x, b4.y, b4.z, b4.w};
#pragma unroll
        for (int i = 0; i < 4; i++) if (!mk[i]) { va[i] = NEG; vb[i] = NEG; }

        float mxa = fmaxf(fmaxf(va[0], va[1]), fmaxf(va[2], va[3]));
        float mxb = fmaxf(fmaxf(vb[0], vb[1]), fmaxf(vb[2], vb[3]));
#pragma unroll
        for (int o = 16; o; o >>= 1) {
            mxa = fmaxf(mxa, __shfl_xor_sync(0xffffffffu, mxa, o));
            mxb = fmaxf(mxb, __shfl_xor_sync(0xffffffffu, mxb, o));
        }
        if (lane == 0) { red[w] = mxa; red[8 + w] = mxb; }
        __syncthreads();
        mxa = red[0]; mxb = red[8];
#pragma unroll
        for (int jj = 1; jj < 8; jj++) { mxa = fmaxf(mxa, red[jj]); mxb = fmaxf(mxb, red[8 + jj]); }
        __syncthreads();

        float sa = 0.f, sb = 0.f;
#pragma unroll
        for (int i = 0; i < 4; i++) {
            va[i] = expf(va[i] - mxa); sa += va[i];
            vb[i] = expf(vb[i] - mxb); sb += vb[i];
        }
#pragma unroll
        for (int o = 16; o; o >>= 1) {
            sa += __shfl_xor_sync(0xffffffffu, sa, o);
            sb += __shfl_xor_sync(0xffffffffu, sb, o);
        }
        if (lane == 0) { red[w] = sa; red[8 + w] = sb; }
        __syncthreads();
        float ta = red[0], tb = red[8];
#pragma unroll
        for (int jj = 1; jj < 8; jj++) { ta += red[jj]; tb += red[8 + jj]; }
        __syncthreads();
        float ia = 1.0f / ta, ib = 1.0f / tb;

        float pa0 = va[0] * ia, pa1 = va[1] * ia, pa2 = va[2] * ia, pa3 = va[3] * ia;
        float pb0 = vb[0] * ib, pb1 = vb[1] * ib, pb2 = vb[2] * ib, pb3 = vb[3] * ib;
        macc[0] += pa0 + pb0; macc[1] += pa1 + pb1;
        macc[2] += pa2 + pb2; macc[3] += pa3 + pb3;
        __half2* da = (__half2*)(ah + (((size_t)(b * NH + h)) * QQL + q) * KKL + k0);
        da[0] = __floats2half2_rn(pa0, pa1);
        da[1] = __floats2half2_rn(pa2, pa3);
        __half2* db = (__half2*)(ah + (((size_t)(b * NH + h + 1)) * QQL + q) * KKL + k0);
        db[0] = __floats2half2_rn(pb0, pb1);
        db[1] = __floats2half2_rn(pb2, pb3);
    }

    float4 mo;
    mo.x = macc[0] * (1.0f / NH); mo.y = macc[1] * (1.0f / NH);
    mo.z = macc[2] * (1.0f / NH); mo.w = macc[3] * (1.0f / NH);
    *(float4*)(mout + ((size_t)bq) * KKL + k0) = mo;
}

// ---------------- AV (mma.sync fp16, cp.async 2-stage) ----------------
#define AVP (128*GS)
#define BVP (64*GS)
__global__ void __launch_bounds__(256, 2) av_kernel(
    const __half* __restrict__ attn, const __half* __restrict__ vt,
    __half* __restrict__ Ch)
{
    __shared__ __half sm[2 * (AVP + BVP)];
    const int tid = threadIdx.x;
    const int lane = tid & 31;
    const int warp = tid >> 5;
    const int wm = warp >> 2, wn = warp & 3;
    const int z = blockIdx.z;
    const int b = z / NH, h = z % NH;
    const size_t bm = (size_t)blockIdx.y * 128;

    const __half* A = attn + (size_t)z * QQL * KKL;
    const __half* W = vt + ((size_t)b * 1024 + h * 64) * 1024;
    const size_t Coff = (size_t)b * QQL * DDIM + h * HDIM;

    const int lrow = tid >> 1;
    const int lseg = (tid & 1) * 16;
    const __half* gA = A + (bm + lrow) * (size_t)KKL + lseg;
    const int soffA = lrow * GS + lseg;
    const int brow = tid >> 2;
    const int bseg = (tid & 3) * 8;
    const __half* gB = W + (size_t)brow * 1024 + bseg;
    const int soffB = brow * GS + bseg;

    const uint32_t smBase = smem_u32(sm);
    const int arow = wm * 64 + (lane & 15);
    const int acol = (lane >> 4) << 3;
    const int bg = lane >> 2;
    const int bt = (lane & 3) << 1;
    const int SP2 = AVP + BVP;

    float acc[4][2][4];
#pragma unroll
    for (int i = 0; i < 4; i++)
#pragma unroll
        for (int jq = 0; jq < 2; jq++)
#pragma unroll
            for (int t = 0; t < 4; t++) acc[i][jq][t] = 0.f;

    auto load_stage = [&](int st, int k0) {
        uint32_t d = smBase + (uint32_t)(st * SP2 + soffA) * 2;
        cpa16(d,      gA + k0);
        cpa16(d + 16, gA + k0 + 8);
        uint32_t db = smBase + (uint32_t)(st * SP2 + AVP + soffB) * 2;
        cpa16(db, gB + k0);
    };

    load_stage(0, 0);
    cpa_commit();

    for (int it = 0; it < 32; it++) {
        if (it + 1 < 32) { load_stage((it + 1) & 1, (it + 1) << 5); cpa_commit(); cpa_wait1(); }
        else cpa_wait0();
        __syncthreads();

        const int st = it & 1;
        const uint32_t aBase = smBase + (uint32_t)(st * SP2) * 2;
        const __half* sB = sm + st * SP2 + AVP;

#pragma unroll
        for (int ks = 0; ks < 32; ks += 16) {
            uint32_t af[4][4];
#pragma unroll
            for (int mi = 0; mi < 4; mi++) {
                uint32_t off = (uint32_t)(((arow + mi * 16) * GS + ks + acol) * 2);
                ldsm_x4(af[mi], aBase + off);
            }
#pragma unroll
            for (int ni = 0; ni < 2; ni++) {
                int bidx = (wn * 16 + ni * 8 + bg) * GS + ks + bt;
                uint32_t b0 = *(const uint32_t*)&sB[bidx];
                uint32_t b1 = *(const uint32_t*)&sB[bidx + 8];
#pragma unroll
                for (int mi = 0; mi < 4; mi++)
                    mma_fp16(acc[mi][ni], af[mi], b0, b1);
            }
        }
        __syncthreads();
    }

    const int gr = lane >> 2;
    const int gc = (lane & 3) << 1;
#pragma unroll
    for (int mi = 0; mi < 4; mi++) {
        size_t r0 = bm + wm * 64 + mi * 16 + gr;
#pragma unroll
        for (int ni = 0; ni < 2; ni++) {
            int c0 = wn * 16 + ni * 8 + gc;
#pragma unroll
            for (int half = 0; half < 2; half++) {
                size_t row = r0 + half * 8;
                size_t o = Coff + row * DDIM + c0;
                *(__half2*)(Ch + o) = __floats2half2_rn(
                    acc[mi][ni][half * 2 + 0], acc[mi][ni][half * 2 + 1]);
            }
        }
    }
}

// ---------------- launch ----------------
extern "C" void kernel_launch(void* const* d_in, const int* in_sizes, int n_in,
                              void* d_out, int out_size)
{
    const float* query      = (const float*)d_in[0];
    const float* key_value  = (const float*)d_in[1];
    const void*  kpm        = d_in[2];
    const float* ln_q_w     = (const float*)d_in[3];
    const float* ln_q_b     = (const float*)d_in[4];
    const float* ln_kv_w    = (const float*)d_in[5];
    const float* ln_kv_b    = (const float*)d_in[6];
    const float* ln_f_w     = (const float*)d_in[7];
    const float* ln_f_b     = (const float*)d_in[8];
    const float* in_proj_w  = (const float*)d_in[9];
    const float* in_proj_b  = (const float*)d_in[10];
    const float* out_proj_w = (const float*)d_in[11];
    const float* out_proj_b = (const float*)d_in[12];
    const float* ffn_w1     = (const float*)d_in[13];
    const float* ffn_b1     = (const float*)d_in[14];
    const float* ffn_w2     = (const float*)d_in[15];
    const float* ffn_b2     = (const float*)d_in[16];

    float* out_x    = (float*)d_out;
    float* out_attn = out_x + (size_t)BB * QQL * DDIM;

    __half *xn16, *qk16, *lnf16, *vt16, *ao16, *h16, *w16, *at16;
    float *vp, *sc, *xb;
    cudaGetSymbolAddress((void**)&xn16,  g_xn16);
    cudaGetSymbolAddress((void**)&qk16,  g_qk16);
    cudaGetSymbolAddress((void**)&lnf16, g_lnf16);
    cudaGetSymbolAddress((void**)&vt16,  g_vt16);
    cudaGetSymbolAddress((void**)&ao16,  g_ao16);
    cudaGetSymbolAddress((void**)&h16,   g_h16);
    cudaGetSymbolAddress((void**)&w16,   g_w16);
    cudaGetSymbolAddress((void**)&at16,  g_attn16);
    cudaGetSymbolAddress((void**)&vp,    g_v);
    cudaGetSymbolAddress((void**)&sc,    g_scores);
    cudaGetSymbolAddress((void**)&xb,    g_x);

    const size_t M1 = (size_t)1024 * 1024;
    const size_t MD = (size_t)MROWS * DDIM;
    const size_t OFF_OUT  = 3 * M1;
    const size_t OFF_FFN1 = 4 * M1;
    const size_t OFF_FFN2 = 8 * M1;

    const int SM1 = 2 * (APLANE + BPLANE) * 2;    //  61440 B
    const int SMS = (SAPL + 2 * SBPL) * 2;        //  73728 B
    cudaFuncSetAttribute(gemm16_kernel,   cudaFuncAttributeMaxDynamicSharedMemorySize, SM1);
    cudaFuncSetAttribute(scores16_kernel, cudaFuncAttributeMaxDynamicSharedMemorySize, SMS);

    detect_mask_kernel<<<1, 256>>>((const unsigned char*)kpm);

    // weight conversion (all fp16)
    tofp16_kernel<<<(unsigned)(3 * M1 / 1024), 256>>>(in_proj_w,  w16,            3 * M1);
    tofp16_kernel<<<(unsigned)(1 * M1 / 1024), 256>>>(out_proj_w, w16 + OFF_OUT,  1 * M1);
    tofp16_kernel<<<(unsigned)(4 * M1 / 1024), 256>>>(ffn_w1,     w16 + OFF_FFN1, 4 * M1);
    tofp16_kernel<<<(unsigned)(4 * M1 / 1024), 256>>>(ffn_w2,     w16 + OFF_FFN2, 4 * M1);

    ln_fp16_kernel<<<MROWS, 256>>>(query,     ln_q_w,  ln_q_b,  xn16);
    ln_fp16_kernel<<<MROWS, 256>>>(key_value, ln_kv_w, ln_kv_b, xn16 + MD);

    // merged q+k proj (z=2, fp16 -> fp16)
    dim3 gqk(DDIM / 128, MROWS / 256, 2);
    gemm16_kernel<<<gqk, 512, SM1>>>(xn16, DDIM, (long)MD,
                                     w16, DDIM, (long)M1,
                                     in_proj_b, DDIM, nullptr,
                                     nullptr, qk16, DDIM, (long)MD,
                                     DDIM, 0);
    // v proj (fp16 -> fp32)
    dim3 g1024(DDIM / 128, MROWS / 256, 1);
    gemm16_kernel<<<g1024, 512, SM1>>>(xn16 + MD, DDIM, 0,
                                       w16 + 2 * M1, DDIM, 0,
                                       in_proj_b + 2 * DDIM, 0, nullptr,
                                       vp, nullptr, DDIM, 0,
                                       DDIM, 0);
    transpose16_kernel<<<dim3(DDIM / 32, MROWS / 32), dim3(32, 8)>>>(vp, vt16);

    // scores (persistent-A, fp16 1-pass)
    dim3 gsc(1, QQL / 256, BB * NH);
    scores16_kernel<<<gsc, 512, SMS>>>(qk16, qk16 + MD, sc);

    softmax_mean_kernel<<<BB * QQL, 256>>>(sc, kpm, at16, out_attn);

    dim3 gav(1, QQL / 128, BB * NH);
    av_kernel<<<gav, 256>>>(at16, vt16, ao16);

    // out_proj + residual (fp16 -> fp32)
    gemm16_kernel<<<g1024, 512, SM1>>>(ao16, DDIM, 0,
                                       w16 + OFF_OUT, DDIM, 0,
                                       out_proj_b, 0, query,
                                       xb, nullptr, DDIM, 0,
                                       DDIM, 0);

    ln_fp16_kernel<<<MROWS, 256>>>(xb, ln_f_w, ln_f_b, lnf16);

    // ffn1 (fp16, gelu -> fp16)
    dim3 gff1(FFD / 128, MROWS / 256, 1);
    gemm16_kernel<<<gff1, 512, SM1>>>(lnf16, DDIM, 0,
                                      w16 + OFF_FFN1, DDIM, 0,
                                      ffn_b1, 0, nullptr,
                                      nullptr, h16, FFD, 0,
                                      DDIM, 1);
    // ffn2 (fp16, residual -> fp32)
    gemm16_kernel<<<g1024, 512, SM1>>>(h16, FFD, 0,
                                       w16 + OFF_FFN2, FFD, 0,
                                       ffn_b2, 0, xb,
                                       out_x, nullptr, DDIM, 0,
                                       FFD, 0);
}

// round 16
// speedup vs baseline: 1.4882x; 1.4882x over previous
#include <cuda_runtime.h>
#include <cuda_bf16.h>
#include <cuda_fp16.h>
#include <math.h>
#include <stdint.h>

#define BB 8
#define QQL 1024
#define KKL 1024
#define DDIM 1024
#define NH 16
#define HDIM 64
#define FFD 4096
#define MROWS (BB*QQL)   /* 8192 */
#define GS 40            /* smem row stride (2B elems) */
#define APLANE (256*GS)
#define BPLANE (128*GS)

// ---------------- scratch (device globals) ----------------
__device__ __half g_xn16[(size_t)3 * MROWS * DDIM];
__device__ __half g_qk16[(size_t)3 * MROWS * DDIM];
__device__ __half g_lnf16[(size_t)MROWS * DDIM];
__device__ __half g_vt16[(size_t)MROWS * DDIM];
__device__ __half g_ao16[(size_t)MROWS * DDIM];
__device__ __half g_h16[(size_t)MROWS * FFD];
__device__ __half g_w16[(size_t)12 * 1024 * 1024];
__device__ __half g_attn16[(size_t)BB * NH * QQL * KKL];     // 256 MB
__device__ float g_scores[(size_t)BB * NH * QQL * KKL];      // 512 MB
__device__ float g_x[(size_t)MROWS * DDIM];
__device__ int   g_mask_flag;

// ---------------- helpers ----------------
__device__ __forceinline__ uint32_t smem_u32(const void* p) {
    return (uint32_t)__cvta_generic_to_shared(p);
}
__device__ __forceinline__ void cpa16(uint32_t dst, const void* src) {
    asm volatile("cp.async.cg.shared.global [%0], [%1], 16;\n" :: "r"(dst), "l"(src));
}
__device__ __forceinline__ void cpa_commit() { asm volatile("cp.async.commit_group;\n"); }
__device__ __forceinline__ void cpa_wait0() { asm volatile("cp.async.wait_group 0;\n"); }
__device__ __forceinline__ void cpa_wait1() { asm volatile("cp.async.wait_group 1;\n"); }
__device__ __forceinline__ void cpa_wait2() { asm volatile("cp.async.wait_group 2;\n"); }

__device__ __forceinline__ void mma_fp16(float* c, const uint32_t* a, uint32_t b0, uint32_t b1) {
    asm volatile(
        "mma.sync.aligned.m16n8k16.row.col.f32.f16.f16.f32 "
        "{%0,%1,%2,%3}, {%4,%5,%6,%7}, {%8,%9}, {%0,%1,%2,%3};\n"
        : "+f"(c[0]), "+f"(c[1]), "+f"(c[2]), "+f"(c[3])
        : "r"(a[0]), "r"(a[1]), "r"(a[2]), "r"(a[3]), "r"(b0), "r"(b1));
}
__device__ __forceinline__ void ldsm_x4(uint32_t* r, uint32_t addr) {
    asm volatile("ldmatrix.sync.aligned.m8n8.x4.shared.b16 {%0,%1,%2,%3}, [%4];\n"
                 : "=r"(r[0]), "=r"(r[1]), "=r"(r[2]), "=r"(r[3]) : "r"(addr));
}
__device__ __forceinline__ float gelu_exact(float v) {
    return 0.5f * v * (1.0f + erff(v * 0.70710678118654752f));
}

// ---------------- mask dtype sniffing ----------------
__global__ void detect_mask_kernel(const unsigned char* __restrict__ m) {
    __shared__ int c1, c2, c3;
    if (threadIdx.x == 0) { c1 = 0; c2 = 0; c3 = 0; }
    __syncthreads();
    for (int i = threadIdx.x; i < BB * KKL; i += blockDim.x) {
        unsigned char v = m[i];
        if (v) {
            int p = i & 3;
            if (p == 1) atomicAdd(&c1, 1);
            else if (p == 2) atomicAdd(&c2, 1);
            else if (p == 3) atomicAdd(&c3, 1);
        }
    }
    __syncthreads();
    if (threadIdx.x == 0) {
        int f;
        if (c1 == 0 && c2 == 0 && c3 == 0) f = 0;  // int32
        else if (c1 == 0) f = 2;                   // float32
        else f = 1;                                // uint8
        g_mask_flag = f;
    }
}

__device__ __forceinline__ bool mask_valid(const void* m, int idx, int flag) {
    if (flag == 1) return ((const unsigned char*)m)[idx] != 0;
    if (flag == 2) return ((const float*)m)[idx] != 0.0f;
    return ((const int*)m)[idx] != 0;
}

// ---------------- convert fp32 -> fp16 ----------------
__global__ void __launch_bounds__(256) tofp16_kernel(
    const float* __restrict__ x, __half* __restrict__ out, size_t n)
{
    size_t i = ((size_t)blockIdx.x * 256 + threadIdx.x) * 4;
    if (i >= n) return;
    float4 v = *(const float4*)(x + i);
    __half2* op = (__half2*)(out + i);
    op[0] = __floats2half2_rn(v.x, v.y);
    op[1] = __floats2half2_rn(v.z, v.w);
}

// ---------------- layernorm -> fp16 (optional duplicate output) ----------------
__global__ void __launch_bounds__(256) ln_fp16_kernel(
    const float* __restrict__ x, const float* __restrict__ w,
    const float* __restrict__ b, __half* __restrict__ out, __half* __restrict__ out2)
{
    int row = blockIdx.x;
    const float* xr = x + (size_t)row * DDIM;
    float sum = 0.f, sumsq = 0.f;
    for (int i = threadIdx.x; i < DDIM; i += blockDim.x) {
        float v = xr[i]; sum += v; sumsq += v * v;
    }
    __shared__ float s1[32], s2[32];
    for (int o = 16; o; o >>= 1) {
        sum   += __shfl_down_sync(0xffffffffu, sum, o);
        sumsq += __shfl_down_sync(0xffffffffu, sumsq, o);
    }
    int lane = threadIdx.x & 31, wid = threadIdx.x >> 5;
    if (lane == 0) { s1[wid] = sum; s2[wid] = sumsq; }
    __syncthreads();
    if (wid == 0) {
        sum   = lane < 8 ? s1[lane] : 0.f;
        sumsq = lane < 8 ? s2[lane] : 0.f;
        for (int o = 4; o; o >>= 1) {
            sum   += __shfl_down_sync(0xffffffffu, sum, o);
            sumsq += __shfl_down_sync(0xffffffffu, sumsq, o);
        }
        if (lane == 0) { s1[0] = sum; s2[0] = sumsq; }
    }
    __syncthreads();
    float mu  = s1[0] * (1.0f / DDIM);
    float var = s2[0] * (1.0f / DDIM) - mu * mu;
    float inv = rsqrtf(var + 1e-5f);
    size_t base = (size_t)row * DDIM;
    for (int i = threadIdx.x; i < DDIM; i += blockDim.x) {
        float v = (xr[i] - mu) * inv * w[i] + b[i];
        __half hv = __float2half_rn(v);
        out[base + i] = hv;
        if (out2) out2[base + i] = hv;
    }
}

// ---------------- fp16 1-pass GEMM, 256x128 tile, 512 threads, 3-stage, z-batch ----------------
__global__ void __launch_bounds__(512, 1) gemm16_kernel(
    const __half* __restrict__ A, long lda, long sAz,
    const __half* __restrict__ W, long ldb, long sBz,
    const float* __restrict__ bias, long sbias, const float* __restrict__ resid,
    float* __restrict__ Cf, __half* __restrict__ Chf, long ldc, long sCz,
    int Kd, int act)
{
    extern __shared__ __half smh[];
    const int SP = APLANE + BPLANE;
    const int offB = APLANE;

    const int tid  = threadIdx.x;
    const int lane = tid & 31;
    const int warp = tid >> 5;
    const int wm = warp >> 2, wn = warp & 3;
    const int z = blockIdx.z;
    const size_t Aoff = (size_t)z * sAz;
    const size_t Boff = (size_t)z * sBz;
    const size_t Coff = (size_t)z * sCz;
    const size_t bm = (size_t)blockIdx.y * 256, bn = (size_t)blockIdx.x * 128;
    const float* bptr = bias ? bias + (size_t)z * sbias : nullptr;

    const int lr   = tid >> 2;
    const int lseg = (tid & 3) * 8;
    const __half* gA1 = A + Aoff + (bm + lr) * (size_t)lda + lseg;
    const __half* gA2 = gA1 + 128 * (size_t)lda;
    const __half* gB  = W + Boff + (bn + lr) * (size_t)ldb + lseg;
    const int soffA1 = lr * GS + lseg;
    const int soffA2 = soffA1 + 128 * GS;
    const int soffB  = lr * GS + lseg;

    const uint32_t smBase = smem_u32(smh);
    const int arow = wm * 64 + (lane & 15);
    const int acol = (lane >> 4) << 3;
    const int bg = lane >> 2;
    const int bt = (lane & 3) << 1;

    float acc[4][4][4];
#pragma unroll
    for (int i = 0; i < 4; i++)
#pragma unroll
        for (int j = 0; j < 4; j++)
#pragma unroll
            for (int t = 0; t < 4; t++) acc[i][j][t] = 0.f;

    const int ntiles = Kd >> 5;

    auto load_stage = [&](int st, int k0) {
        uint32_t base = smBase + (uint32_t)(st * SP) * 2;
        cpa16(base + (uint32_t)soffA1 * 2, gA1 + k0);
        cpa16(base + (uint32_t)soffA2 * 2, gA2 + k0);
        cpa16(base + (uint32_t)(offB + soffB) * 2, gB + k0);
    };

    load_stage(0, 0);
    cpa_commit();
    load_stage(1, 32);
    cpa_commit();

    for (int it = 0; it < ntiles; it++) {
        if (it + 2 < ntiles) { load_stage((it + 2) % 3, (it + 2) << 5); cpa_commit(); cpa_wait2(); }
        else if (it + 1 < ntiles) cpa_wait1();
        else cpa_wait0();
        __syncthreads();

        const int st = it % 3;
        const uint32_t aB = smBase + (uint32_t)(st * SP) * 2;
        const __half* sB = smh + st * SP + offB;

#pragma unroll
        for (int ks = 0; ks < 32; ks += 16) {
            uint32_t af[4][4];
#pragma unroll
            for (int mi = 0; mi < 4; mi++) {
                uint32_t off = (uint32_t)(((arow + mi * 16) * GS + ks + acol) * 2);
                ldsm_x4(af[mi], aB + off);
            }
#pragma unroll
            for (int ni = 0; ni < 4; ni++) {
                int bidx = (wn * 32 + ni * 8 + bg) * GS + ks + bt;
                uint32_t b0 = *(const uint32_t*)&sB[bidx];
                uint32_t b1 = *(const uint32_t*)&sB[bidx + 8];
#pragma unroll
                for (int mi = 0; mi < 4; mi++)
                    mma_fp16(acc[mi][ni], af[mi], b0, b1);
            }
        }
        __syncthreads();
    }

    const int gr = lane >> 2;
    const int gc = (lane & 3) << 1;
#pragma unroll
    for (int mi = 0; mi < 4; mi++) {
        size_t r0 = bm + wm * 64 + mi * 16 + gr;
#pragma unroll
        for (int ni = 0; ni < 4; ni++) {
            size_t c0 = bn + wn * 32 + ni * 8 + gc;
            float bv0 = bptr ? bptr[c0] : 0.f;
            float bv1 = bptr ? bptr[c0 + 1] : 0.f;
#pragma unroll
            for (int half = 0; half < 2; half++) {
                size_t row = r0 + half * 8;
                float v0 = acc[mi][ni][half * 2 + 0] + bv0;
                float v1 = acc[mi][ni][half * 2 + 1] + bv1;
                size_t o = Coff + row * ldc + c0;
                if (resid) {
                    float2 rv = *(const float2*)(resid + o);
                    v0 += rv.x; v1 += rv.y;
                }
                if (act) { v0 = gelu_exact(v0); v1 = gelu_exact(v1); }
                if (Cf)  *(float2*)(Cf + o) = make_float2(v0, v1);
                if (Chf) *(__half2*)(Chf + o) = __floats2half2_rn(v0, v1);
            }
        }
    }
}

// ---------------- dedicated fp16 scores kernel (persistent A) ----------------
#define SGS 72
#define SAPL (256*SGS)
#define SBPL (128*SGS)
__global__ void __launch_bounds__(512, 1) scores16_kernel(
    const __half* __restrict__ qp, const __half* __restrict__ kp,
    float* __restrict__ S)
{
    extern __shared__ __half smh[];
    const int offB = SAPL;
    const int BSTG = SBPL;

    const int tid = threadIdx.x, lane = tid & 31, warp = tid >> 5;
    const int wm = warp >> 2, wn = warp & 3;
    const int z = blockIdx.z, b = z / NH, h = z % NH;
    const size_t bm = (size_t)blockIdx.y * 256;
    const __half* A = qp + (size_t)b * QQL * DDIM + h * HDIM;
    const __half* B = kp + (size_t)b * KKL * DDIM + h * HDIM;
    float* C = S + ((size_t)(b * NH + h) * QQL + bm) * KKL;

    const uint32_t smBase = smem_u32(smh);

    // A: 256 rows x 64 cols fp16, persistent
#pragma unroll
    for (int i = 0; i < 4; i++) {
        int c = tid + 512 * i;
        int row = c >> 3;
        int seg = (c & 7) * 8;
        uint32_t d = smBase + (uint32_t)(row * SGS + seg) * 2;
        cpa16(d, A + (bm + row) * (size_t)DDIM + seg);
    }
    auto load_B = [&](int st, int kt) {
        uint32_t base = smBase + (uint32_t)(offB + st * BSTG) * 2;
#pragma unroll
        for (int i = 0; i < 2; i++) {
            int c = tid + 512 * i;
            int row = c >> 3;
            int seg = (c & 7) * 8;
            cpa16(base + (uint32_t)(row * SGS + seg) * 2,
                  B + (size_t)(kt * 128 + row) * DDIM + seg);
        }
    };
    load_B(0, 0);
    cpa_commit();

    const int arow = wm * 64 + (lane & 15);
    const int acol = (lane >> 4) << 3;
    const int bg = lane >> 2, bt = (lane & 3) << 1;
    const int gr = lane >> 2;
    const int gc = (lane & 3) << 1;

    for (int kt = 0; kt < 8; kt++) {
        if (kt + 1 < 8) { load_B((kt + 1) & 1, kt + 1); cpa_commit(); cpa_wait1(); }
        else cpa_wait0();
        __syncthreads();
        const __half* sB = smh + offB + (kt & 1) * BSTG;

        float acc[4][4][4];
#pragma unroll
        for (int i = 0; i < 4; i++)
#pragma unroll
            for (int j = 0; j < 4; j++)
#pragma unroll
                for (int t = 0; t < 4; t++) acc[i][j][t] = 0.f;

#pragma unroll
        for (int ks = 0; ks < 64; ks += 16) {
            uint32_t af[4][4];
#pragma unroll
            for (int mi = 0; mi < 4; mi++) {
                uint32_t off = (uint32_t)(((arow + mi * 16) * SGS + ks + acol) * 2);
                ldsm_x4(af[mi], smBase + off);
            }
#pragma unroll
            for (int ni = 0; ni < 4; ni++) {
                int bidx = (wn * 32 + ni * 8 + bg) * SGS + ks + bt;
                uint32_t b0 = *(const uint32_t*)&sB[bidx];
                uint32_t b1 = *(const uint32_t*)&sB[bidx + 8];
#pragma unroll
                for (int mi = 0; mi < 4; mi++)
                    mma_fp16(acc[mi][ni], af[mi], b0, b1);
            }
        }

#pragma unroll
        for (int mi = 0; mi < 4; mi++) {
            size_t r0 = wm * 64 + mi * 16 + gr;
#pragma unroll
            for (int ni = 0; ni < 4; ni++) {
                size_t c0 = (size_t)kt * 128 + wn * 32 + ni * 8 + gc;
#pragma unroll
                for (int half = 0; half < 2; half++) {
                    size_t row = r0 + half * 8;
                    *(float2*)(C + row * KKL + c0) = make_float2(
                        acc[mi][ni][half * 2 + 0] * 0.125f,
                        acc[mi][ni][half * 2 + 1] * 0.125f);
                }
            }
        }
        __syncthreads();
    }
}

// ---------------- transpose V (fp16 -> fp16, [b,k,c] -> [b,c,k]) ----------------
__global__ void __launch_bounds__(256) transpose16_kernel(
    const __half* __restrict__ v, __half* __restrict__ th)
{
    __shared__ __half tile[32][33];
    int tx = threadIdx.x, ty = threadIdx.y;
    int c0 = blockIdx.x * 32;
    int r0 = blockIdx.y * 32;
#pragma unroll
    for (int i = 0; i < 4; i++)
        tile[ty + i * 8][tx] = v[(size_t)(r0 + ty + i * 8) * DDIM + c0 + tx];
    __syncthreads();
    int b = r0 >> 10;
    int kk0 = r0 & 1023;
#pragma unroll
    for (int i = 0; i < 4; i++) {
        size_t o = ((size_t)(b << 10) + c0 + ty + i * 8) * 1024 + kk0 + tx;
        th[o] = tile[tx][ty + i * 8];
    }
}

// ---------------- fused masked softmax + head mean (4 heads / iter, fp16 out) ----------------
__global__ void __launch_bounds__(256) softmax_mean_kernel(
    const float* __restrict__ S, const void* __restrict__ mask,
    __half* __restrict__ ah, float* __restrict__ mout)
{
    const int bq = blockIdx.x;
    const int b = bq >> 10, q = bq & 1023;
    const int t = threadIdx.x;
    const int k0 = t * 4;
    const int flag = g_mask_flag;
    const int lane = t & 31, w = t >> 5;

    bool mk[4];
#pragma unroll
    for (int i = 0; i < 4; i++) mk[i] = mask_valid(mask, b * KKL + k0 + i, flag);

    float macc[4] = {0.f, 0.f, 0.f, 0.f};
    __shared__ float red[32];
    const float NEG = -__int_as_float(0x7f800000);

    for (int h = 0; h < NH; h += 4) {
        float v[4][4], mx[4];
#pragma unroll
        for (int g = 0; g < 4; g++) {
            const float* r = S + (((size_t)(b * NH + h + g)) * QQL + q) * KKL;
            float4 v4 = *(const float4*)(r + k0);
            v[g][0] = mk[0] ? v4.x : NEG;
            v[g][1] = mk[1] ? v4.y : NEG;
            v[g][2] = mk[2] ? v4.z : NEG;
            v[g][3] = mk[3] ? v4.w : NEG;
            mx[g] = fmaxf(fmaxf(v[g][0], v[g][1]), fmaxf(v[g][2], v[g][3]));
        }
#pragma unroll
        for (int o = 16; o; o >>= 1)
#pragma unroll
            for (int g = 0; g < 4; g++)
                mx[g] = fmaxf(mx[g], __shfl_xor_sync(0xffffffffu, mx[g], o));
        if (lane == 0)
#pragma unroll
            for (int g = 0; g < 4; g++) red[g * 8 + w] = mx[g];
        __syncthreads();
#pragma unroll
        for (int g = 0; g < 4; g++) {
            float m = red[g * 8];
#pragma unroll
            for (int jj = 1; jj < 8; jj++) m = fmaxf(m, red[g * 8 + jj]);
            mx[g] = m;
        }
        __syncthreads();

        float sm[4];
#pragma unroll
        for (int g = 0; g < 4; g++) {
            float s = 0.f;
#pragma unroll
            for (int i = 0; i < 4; i++) { v[g][i] = __expf(v[g][i] - mx[g]); s += v[g][i]; }
            sm[g] = s;
        }
#pragma unroll
        for (int o = 16; o; o >>= 1)
#pragma unroll
            for (int g = 0; g < 4; g++)
                sm[g] += __shfl_xor_sync(0xffffffffu, sm[g], o);
        if (lane == 0)
#pragma unroll
            for (int g = 0; g < 4; g++) red[g * 8 + w] = sm[g];
        __syncthreads();
#pragma unroll
        for (int g = 0; g < 4; g++) {
            float s = red[g * 8];
#pragma unroll
            for (int jj = 1; jj < 8; jj++) s += red[g * 8 + jj];
            sm[g] = 1.0f / s;
        }
        __syncthreads();

#pragma unroll
        for (int g = 0; g < 4; g++) {
            float p0 = v[g][0] * sm[g], p1 = v[g][1] * sm[g];
            float p2 = v[g][2] * sm[g], p3 = v[g][3] * sm[g];
            macc[0] += p0; macc[1] += p1; macc[2] += p2; macc[3] += p3;
            __half2* d = (__half2*)(ah + (((size_t)(b * NH + h + g)) * QQL + q) * KKL + k0);
            d[0] = __floats2half2_rn(p0, p1);
            d[1] = __floats2half2_rn(p2, p3);
        }
    }

    float4 mo;
    mo.x = macc[0] * (1.0f / NH); mo.y = macc[1] * (1.0f / NH);
    mo.z = macc[2] * (1.0f / NH); mo.w = macc[3] * (1.0f / NH);
    *(float4*)(mout + ((size_t)bq) * KKL + k0) = mo;
}

// ---------------- AV (mma.sync fp16, cp.async 2-stage) ----------------
#define AVP (128*GS)
#define BVP (64*GS)
__global__ void __launch_bounds__(256, 2) av_kernel(
    const __half* __restrict__ attn, const __half* __restrict__ vt,
    __half* __restrict__ Ch)
{
    __shared__ __half sm[2 * (AVP + BVP)];
    const int tid = threadIdx.x;
    const int lane = tid & 31;
    const int warp = tid >> 5;
    const int wm = warp >> 2, wn = warp & 3;
    const int z = blockIdx.z;
    const int b = z / NH, h = z % NH;
    const size_t bm = (size_t)blockIdx.y * 128;

    const __half* A = attn + (size_t)z * QQL * KKL;
    const __half* W = vt + ((size_t)b * 1024 + h * 64) * 1024;
    const size_t Coff = (size_t)b * QQL * DDIM + h * HDIM;

    const int lrow = tid >> 1;
    const int lseg = (tid & 1) * 16;
    const __half* gA = A + (bm + lrow) * (size_t)KKL + lseg;
    const int soffA = lrow * GS + lseg;
    const int brow = tid >> 2;
    const int bseg = (tid & 3) * 8;
    const __half* gB = W + (size_t)brow * 1024 + bseg;
    const int soffB = brow * GS + bseg;

    const uint32_t smBase = smem_u32(sm);
    const int arow = wm * 64 + (lane & 15);
    const int acol = (lane >> 4) << 3;
    const int bg = lane >> 2;
    const int bt = (lane & 3) << 1;
    const int SP2 = AVP + BVP;

    float acc[4][2][4];
#pragma unroll
    for (int i = 0; i < 4; i++)
#pragma unroll
        for (int jq = 0; jq < 2; jq++)
#pragma unroll
            for (int t = 0; t < 4; t++) acc[i][jq][t] = 0.f;

    auto load_stage = [&](int st, int k0) {
        uint32_t d = smBase + (uint32_t)(st * SP2 + soffA) * 2;
        cpa16(d,      gA + k0);
        cpa16(d + 16, gA + k0 + 8);
        uint32_t db = smBase + (uint32_t)(st * SP2 + AVP + soffB) * 2;
        cpa16(db, gB + k0);
    };

    load_stage(0, 0);
    cpa_commit();

    for (int it = 0; it < 32; it++) {
        if (it + 1 < 32) { load_stage((it + 1) & 1, (it + 1) << 5); cpa_commit(); cpa_wait1(); }
        else cpa_wait0();
        __syncthreads();

        const int st = it & 1;
        const uint32_t aBase = smBase + (uint32_t)(st * SP2) * 2;
        const __half* sB = sm + st * SP2 + AVP;

#pragma unroll
        for (int ks = 0; ks < 32; ks += 16) {
            uint32_t af[4][4];
#pragma unroll
            for (int mi = 0; mi < 4; mi++) {
                uint32_t off = (uint32_t)(((arow + mi * 16) * GS + ks + acol) * 2);
                ldsm_x4(af[mi], aBase + off);
            }
#pragma unroll
            for (int ni = 0; ni < 2; ni++) {
                int bidx = (wn * 16 + ni * 8 + bg) * GS + ks + bt;
                uint32_t b0 = *(const uint32_t*)&sB[bidx];
                uint32_t b1 = *(const uint32_t*)&sB[bidx + 8];
#pragma unroll
                for (int mi = 0; mi < 4; mi++)
                    mma_fp16(acc[mi][ni], af[mi], b0, b1);
            }
        }
        __syncthreads();
    }

    const int gr = lane >> 2;
    const int gc = (lane & 3) << 1;
#pragma unroll
    for (int mi = 0; mi < 4; mi++) {
        size_t r0 = bm + wm * 64 + mi * 16 + gr;
#pragma unroll
        for (int ni = 0; ni < 2; ni++) {
            int c0 = wn * 16 + ni * 8 + gc;
#pragma unroll
            for (int half = 0; half < 2; half++) {
                size_t row = r0 + half * 8;
                size_t o = Coff + row * DDIM + c0;
                *(__half2*)(Ch + o) = __floats2half2_rn(
                    acc[mi][ni][half * 2 + 0], acc[mi][ni][half * 2 + 1]);
            }
        }
    }
}

// ---------------- launch ----------------
extern "C" void kernel_launch(void* const* d_in, const int* in_sizes, int n_in,
                              void* d_out, int out_size)
{
    const float* query      = (const float*)d_in[0];
    const float* key_value  = (const float*)d_in[1];
    const void*  kpm        = d_in[2];
    const float* ln_q_w     = (const float*)d_in[3];
    const float* ln_q_b     = (const float*)d_in[4];
    const float* ln_kv_w    = (const float*)d_in[5];
    const float* ln_kv_b    = (const float*)d_in[6];
    const float* ln_f_w     = (const float*)d_in[7];
    const float* ln_f_b     = (const float*)d_in[8];
    const float* in_proj_w  = (const float*)d_in[9];
    const float* in_proj_b  = (const float*)d_in[10];
    const float* out_proj_w = (const float*)d_in[11];
    const float* out_proj_b = (const float*)d_in[12];
    const float* ffn_w1     = (const float*)d_in[13];
    const float* ffn_b1     = (const float*)d_in[14];
    const float* ffn_w2     = (const float*)d_in[15];
    const float* ffn_b2     = (const float*)d_in[16];

    float* out_x    = (float*)d_out;
    float* out_attn = out_x + (size_t)BB * QQL * DDIM;

    __half *xn16, *qk16, *lnf16, *vt16, *ao16, *h16, *w16, *at16;
    float *sc, *xb;
    cudaGetSymbolAddress((void**)&xn16,  g_xn16);
    cudaGetSymbolAddress((void**)&qk16,  g_qk16);
    cudaGetSymbolAddress((void**)&lnf16, g_lnf16);
    cudaGetSymbolAddress((void**)&vt16,  g_vt16);
    cudaGetSymbolAddress((void**)&ao16,  g_ao16);
    cudaGetSymbolAddress((void**)&h16,   g_h16);
    cudaGetSymbolAddress((void**)&w16,   g_w16);
    cudaGetSymbolAddress((void**)&at16,  g_attn16);
    cudaGetSymbolAddress((void**)&sc,    g_scores);
    cudaGetSymbolAddress((void**)&xb,    g_x);

    const size_t M1 = (size_t)1024 * 1024;
    const size_t MD = (size_t)MROWS * DDIM;
    const size_t OFF_OUT  = 3 * M1;
    const size_t OFF_FFN1 = 4 * M1;
    const size_t OFF_FFN2 = 8 * M1;

    const int SM1 = 3 * (APLANE + BPLANE) * 2;    //  92160 B (3-stage)
    const int SMS = (SAPL + 2 * SBPL) * 2;        //  73728 B
    cudaFuncSetAttribute(gemm16_kernel,   cudaFuncAttributeMaxDynamicSharedMemorySize, SM1);
    cudaFuncSetAttribute(scores16_kernel, cudaFuncAttributeMaxDynamicSharedMemorySize, SMS);

    detect_mask_kernel<<<1, 256>>>((const unsigned char*)kpm);

    // weight conversion (all fp16)
    tofp16_kernel<<<(unsigned)(3 * M1 / 1024), 256>>>(in_proj_w,  w16,            3 * M1);
    tofp16_kernel<<<(unsigned)(1 * M1 / 1024), 256>>>(out_proj_w, w16 + OFF_OUT,  1 * M1);
    tofp16_kernel<<<(unsigned)(4 * M1 / 1024), 256>>>(ffn_w1,     w16 + OFF_FFN1, 4 * M1);
    tofp16_kernel<<<(unsigned)(4 * M1 / 1024), 256>>>(ffn_w2,     w16 + OFF_FFN2, 4 * M1);

    // layernorms; kv output duplicated for the z=3 batched projection
    ln_fp16_kernel<<<MROWS, 256>>>(query,     ln_q_w,  ln_q_b,  xn16,      nullptr);
    ln_fp16_kernel<<<MROWS, 256>>>(key_value, ln_kv_w, ln_kv_b, xn16 + MD, xn16 + 2 * MD);

    // merged q+k+v proj (z=3, fp16 -> fp16)
    dim3 gqkv(DDIM / 128, MROWS / 256, 3);
    gemm16_kernel<<<gqkv, 512, SM1>>>(xn16, DDIM, (long)MD,
                                      w16, DDIM, (long)M1,
                                      in_proj_b, DDIM, nullptr,
                                      nullptr, qk16, DDIM, (long)MD,
                                      DDIM, 0);
    // V transpose ([b,k,c] -> [b,c,k])
    transpose16_kernel<<<dim3(DDIM / 32, MROWS / 32), dim3(32, 8)>>>(qk16 + 2 * MD, vt16);

    // scores (persistent-A, fp16 1-pass)
    dim3 gsc(1, QQL / 256, BB * NH);
    scores16_kernel<<<gsc, 512, SMS>>>(qk16, qk16 + MD, sc);

    softmax_mean_kernel<<<BB * QQL, 256>>>(sc, kpm, at16, out_attn);

    dim3 gav(1, QQL / 128, BB * NH);
    av_kernel<<<gav, 256>>>(at16, vt16, ao16);

    // out_proj + residual (fp16 -> fp32)
    dim3 g1024(DDIM / 128, MROWS / 256, 1);
    gemm16_kernel<<<g1024, 512, SM1>>>(ao16, DDIM, 0,
                                       w16 + OFF_OUT, DDIM, 0,
                                       out_proj_b, 0, query,
                                       xb, nullptr, DDIM, 0,
                                       DDIM, 0);

    ln_fp16_kernel<<<MROWS, 256>>>(xb, ln_f_w, ln_f_b, lnf16, nullptr);

    // ffn1 (fp16, gelu -> fp16)
    dim3 gff1(FFD / 128, MROWS / 256, 1);
    gemm16_kernel<<<gff1, 512, SM1>>>(lnf16, DDIM, 0,
                                      w16 + OFF_FFN1, DDIM, 0,
                                      ffn_b1, 0, nullptr,
                                      nullptr, h16, FFD, 0,
                                      DDIM, 1);
    // ffn2 (fp16, residual -> fp32)
    gemm16_kernel<<<g1024, 512, SM1>>>(h16, FFD, 0,
                                       w16 + OFF_FFN2, FFD, 0,
                                       ffn_b2, 0, xb,
                                       out_x, nullptr, DDIM, 0,
                                       FFD, 0);
}